// round 2
// baseline (speedup 1.0000x reference)
#include <cuda_runtime.h>
#include <cstdint>

#define T_TOKENS 16384
#define DDIM     4096
#define NEXP     64
#define MT       64      // tokens per CTA
#define KT       32      // K chunk
#define NTH      256
#define NC       (DDIM / KT)   // 128 chunks
#define LSTRIDE  65      // padded logits row stride (conflict-free scalar reads)

// ---- packed f32x2 helpers (sm_103a PTX) ----
__device__ __forceinline__ void fma2(unsigned long long& acc,
                                     unsigned long long a, unsigned long long b) {
    asm("fma.rn.f32x2 %0, %1, %2, %0;" : "+l"(acc) : "l"(a), "l"(b));
}
__device__ __forceinline__ void unpack2(unsigned long long v, float& lo, float& hi) {
    asm("mov.b64 {%0, %1}, %2;" : "=f"(lo), "=f"(hi) : "l"(v));
}

// smem: hbuf[2][KT][MT] = 4096 f, wdup[2][KT][2*NEXP] = 8192 f  -> 12288 f = 48KB
// epilogue reuses as logits [64][LSTRIDE]
#define HBUF(b)  (sbuf + (b) * (KT * MT))
#define WBUF(b)  (sbuf + 4096 + (b) * (KT * 2 * NEXP))

__global__ __launch_bounds__(NTH)
void gate_kernel(const float* __restrict__ h,
                 const float* __restrict__ W,
                 float* __restrict__ out)
{
    __shared__ __align__(16) float sbuf[12288];
    const int tid = threadIdx.x;

    // ---- loader mapping: each thread loads 8 consecutive k for one row ----
    const int lr  = tid >> 2;          // row: token or expert, 0..63
    const int lc  = (tid & 3) * 8;     // k offset within chunk: 0,8,16,24
    const int lg  = tid & 3;           // swizzle group = (k>>3) for all 8 stores
    const int hrs = lr ^ (lg << 3);            // swizzled token index (h store)
    const int wfs = (2 * lr) ^ (lg << 3);      // swizzled dup-float index (W store)

    // ---- compute mapping: 4 tokens x 4 experts per thread ----
    const int tx4 = (tid & 15) * 4;    // token base
    const int ty  = tid >> 4;          // expert group (experts ty*4..+3)
    int hoff[4], woff[4];              // swizzled read bases per k-group
#pragma unroll
    for (int g = 0; g < 4; g++) {
        hoff[g] = tx4      ^ (g << 3);
        woff[g] = (ty * 8) ^ (g << 3);
    }

    const float* hgp = h + (size_t)blockIdx.x * MT * DDIM + (size_t)lr * DDIM + lc;
    const float* wgp = W + (size_t)lr * DDIM + lc;

    unsigned long long acc[2][4];
#pragma unroll
    for (int i = 0; i < 2; i++)
#pragma unroll
        for (int j = 0; j < 4; j++) acc[i][j] = 0ULL;

    float4 ha0, ha1, wa0, wa1;

    // ---- prologue: load + store chunk 0 ----
    ha0 = *(const float4*)(hgp);
    ha1 = *(const float4*)(hgp + 4);
    wa0 = *(const float4*)(wgp);
    wa1 = *(const float4*)(wgp + 4);
    {
        float* hb = HBUF(0);
        float* wb = WBUF(0);
        hb[(lc + 0) * MT + hrs] = ha0.x;
        hb[(lc + 1) * MT + hrs] = ha0.y;
        hb[(lc + 2) * MT + hrs] = ha0.z;
        hb[(lc + 3) * MT + hrs] = ha0.w;
        hb[(lc + 4) * MT + hrs] = ha1.x;
        hb[(lc + 5) * MT + hrs] = ha1.y;
        hb[(lc + 6) * MT + hrs] = ha1.z;
        hb[(lc + 7) * MT + hrs] = ha1.w;
        *(float2*)(wb + (lc + 0) * 128 + wfs) = make_float2(wa0.x, wa0.x);
        *(float2*)(wb + (lc + 1) * 128 + wfs) = make_float2(wa0.y, wa0.y);
        *(float2*)(wb + (lc + 2) * 128 + wfs) = make_float2(wa0.z, wa0.z);
        *(float2*)(wb + (lc + 3) * 128 + wfs) = make_float2(wa0.w, wa0.w);
        *(float2*)(wb + (lc + 4) * 128 + wfs) = make_float2(wa1.x, wa1.x);
        *(float2*)(wb + (lc + 5) * 128 + wfs) = make_float2(wa1.y, wa1.y);
        *(float2*)(wb + (lc + 6) * 128 + wfs) = make_float2(wa1.z, wa1.z);
        *(float2*)(wb + (lc + 7) * 128 + wfs) = make_float2(wa1.w, wa1.w);
    }

    for (int kc = 0; kc < NC; ++kc) {
        __syncthreads();   // buf(kc&1) written; buf((kc+1)&1) readers done

        if (kc + 1 < NC) {
            const float* hg = hgp + (kc + 1) * KT;
            const float* wg = wgp + (kc + 1) * KT;
            ha0 = *(const float4*)(hg);
            ha1 = *(const float4*)(hg + 4);
            wa0 = *(const float4*)(wg);
            wa1 = *(const float4*)(wg + 4);
        }

        const float* hb = HBUF(kc & 1);
        const float* wb = WBUF(kc & 1);
#pragma unroll
        for (int ki = 0; ki < KT; ++ki) {
            const int g = ki >> 3;
            ulonglong2 hv = *(const ulonglong2*)(hb + ki * MT  + hoff[g]);
            ulonglong2 w0 = *(const ulonglong2*)(wb + ki * 128 + woff[g]);
            ulonglong2 w1 = *(const ulonglong2*)(wb + ki * 128 + woff[g] + 4);
            fma2(acc[0][0], hv.x, w0.x);
            fma2(acc[0][1], hv.x, w0.y);
            fma2(acc[0][2], hv.x, w1.x);
            fma2(acc[0][3], hv.x, w1.y);
            fma2(acc[1][0], hv.y, w0.x);
            fma2(acc[1][1], hv.y, w0.y);
            fma2(acc[1][2], hv.y, w1.x);
            fma2(acc[1][3], hv.y, w1.y);
        }

        if (kc + 1 < NC) {
            float* hn = HBUF((kc + 1) & 1);
            float* wn = WBUF((kc + 1) & 1);
            hn[(lc + 0) * MT + hrs] = ha0.x;
            hn[(lc + 1) * MT + hrs] = ha0.y;
            hn[(lc + 2) * MT + hrs] = ha0.z;
            hn[(lc + 3) * MT + hrs] = ha0.w;
            hn[(lc + 4) * MT + hrs] = ha1.x;
            hn[(lc + 5) * MT + hrs] = ha1.y;
            hn[(lc + 6) * MT + hrs] = ha1.z;
            hn[(lc + 7) * MT + hrs] = ha1.w;
            *(float2*)(wn + (lc + 0) * 128 + wfs) = make_float2(wa0.x, wa0.x);
            *(float2*)(wn + (lc + 1) * 128 + wfs) = make_float2(wa0.y, wa0.y);
            *(float2*)(wn + (lc + 2) * 128 + wfs) = make_float2(wa0.z, wa0.z);
            *(float2*)(wn + (lc + 3) * 128 + wfs) = make_float2(wa0.w, wa0.w);
            *(float2*)(wn + (lc + 4) * 128 + wfs) = make_float2(wa1.x, wa1.x);
            *(float2*)(wn + (lc + 5) * 128 + wfs) = make_float2(wa1.y, wa1.y);
            *(float2*)(wn + (lc + 6) * 128 + wfs) = make_float2(wa1.z, wa1.z);
            *(float2*)(wn + (lc + 7) * 128 + wfs) = make_float2(wa1.w, wa1.w);
        }
    }

    // ---- epilogue: logits -> smem ----
    __syncthreads();   // all GEMM smem reads done; safe to overwrite
#pragma unroll
    for (int tp = 0; tp < 2; tp++) {
#pragma unroll
        for (int p = 0; p < 4; p++) {
            float lo, hi;
            unpack2(acc[tp][p], lo, hi);
            const int t = tx4 + tp * 2;
            const int e = ty * 4 + p;
            sbuf[(t + 0) * LSTRIDE + e] = lo;
            sbuf[(t + 1) * LSTRIDE + e] = hi;
        }
    }
    __syncthreads();

    // ---- per-token softmax + top-2 (64 threads) ----
    if (tid < MT) {
        const float* row = sbuf + tid * LSTRIDE;
        float v1 = -1e30f, v2 = -1e30f;
        int   i1 = 0,      i2 = 0;
#pragma unroll 8
        for (int e = 0; e < NEXP; ++e) {
            float l = row[e];
            if (l > v1) { v2 = v1; i2 = i1; v1 = l; i1 = e; }
            else if (l > v2) { v2 = l; i2 = e; }
        }
        float S = 0.f;
#pragma unroll 8
        for (int e = 0; e < NEXP; ++e) S += __expf(row[e] - v1);
        const float e1 = __expf(v2 - v1);
        const float denom = 1.0f + e1 + 1e-9f * S;
        const float w0 = 1.0f / denom;
        const float w1 = e1 / denom;

        const size_t gt = (size_t)blockIdx.x * MT + tid;
        out[gt * 2 + 0] = w0;
        out[gt * 2 + 1] = w1;
        out[(size_t)2 * T_TOKENS + gt * 2 + 0] = (float)i1;
        out[(size_t)2 * T_TOKENS + gt * 2 + 1] = (float)i2;
    }
}

extern "C" void kernel_launch(void* const* d_in, const int* in_sizes, int n_in,
                              void* d_out, int out_size)
{
    const float* h = (const float*)d_in[0];
    const float* W = (const float*)d_in[1];
    float* out = (float*)d_out;
    gate_kernel<<<T_TOKENS / MT, NTH>>>(h, W, out);
}

// round 5
// speedup vs baseline: 2.3199x; 2.3199x over previous
#include <cuda_runtime.h>
#include <cuda_bf16.h>
#include <cstdint>

#define TTOK  16384
#define DDIM  4096
#define NEXP  64
#define MROWS 128               // tokens per CTA
#define KC    64                // k per chunk (64 bf16 = 128B rows, SW128)
#define NCH   (DDIM / KC)       // 64 chunks
#define NTH   256

#define SWZ(x) ((x) ^ (((x) >> 3) & 0x70))

// smem: A planes [buf][3][128*128B], B planes [buf][3][64*128B]
#define A_TILE 16384
#define B_TILE 8192
#define SOFF_A 0
#define SOFF_B (6 * A_TILE)                 // 98304
#define SMEM_TOTAL (SOFF_B + 6 * B_TILE)    // 147456 (144KB)

// W pre-split planes, already in swizzled tile layout: [kc][plane][tile 8KB]
__device__ __align__(16) uint32_t gWs[NCH * 3 * 2048];

// ---- exact 3-way bf16 split of two floats -> 3 packed bf16x2 words ----
__device__ __forceinline__ void split2(float x0, float x1,
                                       uint32_t& w0, uint32_t& w1, uint32_t& w2) {
    const uint32_t M = 0xFFFF0000u;
    uint32_t u0 = __float_as_uint(x0), u1 = __float_as_uint(x1);
    float r0 = x0 - __uint_as_float(u0 & M);
    float r1 = x1 - __uint_as_float(u1 & M);
    uint32_t v0 = __float_as_uint(r0), v1 = __float_as_uint(r1);
    float s0 = r0 - __uint_as_float(v0 & M);
    float s1 = r1 - __uint_as_float(v1 & M);
    w0 = __byte_perm(u0, u1, 0x7632);
    w1 = __byte_perm(v0, v1, 0x7632);
    w2 = __byte_perm(__float_as_uint(s0), __float_as_uint(s1), 0x7632);
}

__device__ __forceinline__ uint32_t s2u(const void* p) {
    uint32_t a;
    asm("{ .reg .u64 t; cvta.to.shared.u64 t, %1; cvt.u32.u64 %0, t; }" : "=r"(a) : "l"(p));
    return a;
}

__device__ __forceinline__ void ldm4(uint32_t* r, uint32_t addr) {
    asm volatile("ldmatrix.sync.aligned.m8n8.x4.shared.b16 {%0,%1,%2,%3}, [%4];"
                 : "=r"(r[0]), "=r"(r[1]), "=r"(r[2]), "=r"(r[3]) : "r"(addr));
}

__device__ __forceinline__ void mma16816(float* d, const uint32_t* a,
                                         uint32_t b0, uint32_t b1) {
    asm volatile("mma.sync.aligned.m16n8k16.row.col.f32.bf16.bf16.f32 "
                 "{%0,%1,%2,%3}, {%4,%5,%6,%7}, {%8,%9}, {%0,%1,%2,%3};"
                 : "+f"(d[0]), "+f"(d[1]), "+f"(d[2]), "+f"(d[3])
                 : "r"(a[0]), "r"(a[1]), "r"(a[2]), "r"(a[3]), "r"(b0), "r"(b1));
}

// ---- kernel 0: split W once into swizzled bf16 plane tiles ----
__global__ __launch_bounds__(256)
void split_w_kernel(const float* __restrict__ W) {
    const int j = blockIdx.x * 256 + threadIdx.x;   // pair index, 0..131071
    const int e  = j >> 11;                          // expert 0..63
    const int k0 = (j & 2047) << 1;                  // even k
    float x0 = W[e * DDIM + k0];
    float x1 = W[e * DDIM + k0 + 1];
    uint32_t w0, w1, w2;
    split2(x0, x1, w0, w1, w2);
    const int kc  = k0 >> 6;
    const int off = SWZ(e * 128 + (k0 & 63) * 2) >> 2;   // u32 index in tile
    gWs[(kc * 3 + 0) * 2048 + off] = w0;
    gWs[(kc * 3 + 1) * 2048 + off] = w1;
    gWs[(kc * 3 + 2) * 2048 + off] = w2;
}

// ---- main kernel ----
__global__ __launch_bounds__(NTH)
void gate_kernel(const float* __restrict__ h, float* __restrict__ out)
{
    extern __shared__ __align__(16) char smem[];
    const uint32_t sbase = s2u(smem);
    const int tid = threadIdx.x;
    const int wid = tid >> 5;
    const int lid = tid & 31;

    const float* hblk = h + (size_t)blockIdx.x * MROWS * DDIM;
    const uint4* gw = (const uint4*)gWs;   // 1536 uint4 per chunk (3 planes)

    float acc[8][4];
#pragma unroll
    for (int f = 0; f < 8; f++)
#pragma unroll
        for (int c = 0; c < 4; c++) acc[f][c] = 0.f;

    float4 areg[8];
    uint4  breg[6];

    // ---- prologue: chunk 0 into regs, then smem buf0 ----
#pragma unroll
    for (int i = 0; i < 8; i++) {
        const int q = tid + NTH * i;
        areg[i] = *(const float4*)(hblk + (size_t)(q >> 4) * DDIM + (q & 15) * 4);
    }
#pragma unroll
    for (int i = 0; i < 6; i++) breg[i] = gw[tid + NTH * i];

    {
        char* ab = smem + SOFF_A;     // buf 0
#pragma unroll
        for (int i = 0; i < 8; i++) {
            const int q = tid + NTH * i;
            uint32_t a0, a1, a2, b0, b1, b2;
            split2(areg[i].x, areg[i].y, a0, a1, a2);
            split2(areg[i].z, areg[i].w, b0, b1, b2);
            const int off = SWZ((q >> 4) * 128 + (q & 15) * 8);
            *(uint2*)(ab + off)              = make_uint2(a0, b0);
            *(uint2*)(ab + A_TILE + off)     = make_uint2(a1, b1);
            *(uint2*)(ab + 2 * A_TILE + off) = make_uint2(a2, b2);
        }
        char* bb = smem + SOFF_B;
#pragma unroll
        for (int i = 0; i < 6; i++)
            *(uint4*)(bb + (tid + NTH * i) * 16) = breg[i];
    }
    __syncthreads();

    // per-lane ldmatrix address components
    const int arow = (wid << 4) + (lid & 15);
    const int aoffp = arow * 128;
    const int ax  = (lid >> 4) << 4;          // 0/16: k half
    const int arx = (arow & 7) << 4;
    const int brow = ((lid >> 4) << 3) + (lid & 7);   // n offset within 16
    const int bx  = ((lid >> 3) & 1) << 4;
    const int brx = (lid & 7) << 4;

    for (int kc = 0; kc < NCH; ++kc) {
        // prefetch next chunk into registers
        if (kc + 1 < NCH) {
            const float* hp = hblk + (kc + 1) * KC;
#pragma unroll
            for (int i = 0; i < 8; i++) {
                const int q = tid + NTH * i;
                areg[i] = *(const float4*)(hp + (size_t)(q >> 4) * DDIM + (q & 15) * 4);
            }
            const uint4* gp = gw + (size_t)(kc + 1) * 1536;
#pragma unroll
            for (int i = 0; i < 6; i++) breg[i] = gp[tid + NTH * i];
        }

        // ---- MMA on current buffer ----
        const int buf = kc & 1;
        const uint32_t sA = sbase + SOFF_A + buf * 3 * A_TILE;
        const uint32_t sB = sbase + SOFF_B + buf * 3 * B_TILE;
#pragma unroll
        for (int ks = 0; ks < 4; ++ks) {
            uint32_t a[3][4];
#pragma unroll
            for (int s = 0; s < 3; s++)
                ldm4(a[s], sA + s * A_TILE + aoffp + ((ks * 32 + ax) ^ arx));
#pragma unroll
            for (int nbi = 0; nbi < 4; ++nbi) {
                uint32_t b[3][4];
#pragma unroll
                for (int s = 0; s < 3; s++)
                    ldm4(b[s], sB + s * B_TILE + (nbi * 16 + brow) * 128
                               + ((ks * 32 + bx) ^ brx));
                const int f = nbi * 2;
                // 6 split products: hh, hm, mh, mm, hl, lh
                mma16816(acc[f], a[0], b[0][0], b[0][1]);
                mma16816(acc[f + 1], a[0], b[0][2], b[0][3]);
                mma16816(acc[f], a[0], b[1][0], b[1][1]);
                mma16816(acc[f + 1], a[0], b[1][2], b[1][3]);
                mma16816(acc[f], a[1], b[0][0], b[0][1]);
                mma16816(acc[f + 1], a[1], b[0][2], b[0][3]);
                mma16816(acc[f], a[1], b[1][0], b[1][1]);
                mma16816(acc[f + 1], a[1], b[1][2], b[1][3]);
                mma16816(acc[f], a[0], b[2][0], b[2][1]);
                mma16816(acc[f + 1], a[0], b[2][2], b[2][3]);
                mma16816(acc[f], a[2], b[0][0], b[0][1]);
                mma16816(acc[f + 1], a[2], b[0][2], b[0][3]);
            }
        }

        // ---- store prefetched chunk into other buffer ----
        if (kc + 1 < NCH) {
            const int nb = (kc + 1) & 1;
            char* ab = smem + SOFF_A + nb * 3 * A_TILE;
#pragma unroll
            for (int i = 0; i < 8; i++) {
                const int q = tid + NTH * i;
                uint32_t a0, a1, a2, b0, b1, b2;
                split2(areg[i].x, areg[i].y, a0, a1, a2);
                split2(areg[i].z, areg[i].w, b0, b1, b2);
                const int off = SWZ((q >> 4) * 128 + (q & 15) * 8);
                *(uint2*)(ab + off)              = make_uint2(a0, b0);
                *(uint2*)(ab + A_TILE + off)     = make_uint2(a1, b1);
                *(uint2*)(ab + 2 * A_TILE + off) = make_uint2(a2, b2);
            }
            char* bb = smem + SOFF_B + nb * 3 * B_TILE;
#pragma unroll
            for (int i = 0; i < 6; i++)
                *(uint4*)(bb + (tid + NTH * i) * 16) = breg[i];
        }
        __syncthreads();
    }

    // ---- epilogue: transpose logits to smem [128][66] ----
    float* lg = (float*)smem;
    const int rlo = (wid << 4) + (lid >> 2);
    const int cb  = (lid & 3) << 1;
#pragma unroll
    for (int f = 0; f < 8; f++) {
        *(float2*)(lg + rlo * 66 + f * 8 + cb)       = make_float2(acc[f][0], acc[f][1]);
        *(float2*)(lg + (rlo + 8) * 66 + f * 8 + cb) = make_float2(acc[f][2], acc[f][3]);
    }
    __syncthreads();

    if (tid < MROWS) {
        const float* row = lg + tid * 66;
        float v1 = -1e30f, v2 = -1e30f;
        int i1 = 0, i2 = 0;
#pragma unroll 8
        for (int e = 0; e < NEXP; ++e) {
            float l = row[e];
            if (l > v1) { v2 = v1; i2 = i1; v1 = l; i1 = e; }
            else if (l > v2) { v2 = l; i2 = e; }
        }
        float S = 0.f;
#pragma unroll 8
        for (int e = 0; e < NEXP; ++e) S += __expf(row[e] - v1);
        const float e1  = __expf(v2 - v1);
        const float den = 1.0f + e1 + 1e-9f * S;

        const size_t gt = (size_t)blockIdx.x * MROWS + tid;
        out[gt * 2 + 0] = 1.0f / den;
        out[gt * 2 + 1] = e1 / den;
        out[(size_t)2 * TTOK + gt * 2 + 0] = (float)i1;
        out[(size_t)2 * TTOK + gt * 2 + 1] = (float)i2;
    }
}

extern "C" void kernel_launch(void* const* d_in, const int* in_sizes, int n_in,
                              void* d_out, int out_size)
{
    const float* h = (const float*)d_in[0];
    const float* W = (const float*)d_in[1];
    float* out = (float*)d_out;

    split_w_kernel<<<512, 256>>>(W);

    static int smem_set = 0;
    if (!smem_set) {
        cudaFuncSetAttribute(gate_kernel, cudaFuncAttributeMaxDynamicSharedMemorySize,
                             SMEM_TOTAL);
        smem_set = 1;
    }
    gate_kernel<<<TTOK / MROWS, NTH, SMEM_TOTAL>>>(h, out);
}

// round 6
// speedup vs baseline: 2.3756x; 1.0240x over previous
#include <cuda_runtime.h>
#include <cuda_bf16.h>
#include <cstdint>

#define TTOK  16384
#define DDIM  4096
#define NEXP  64
#define MROWS 64                // tokens per CTA
#define KC    64                // k per chunk (64 bf16 = 128B rows, SW128)
#define NCH   (DDIM / KC)       // 64 chunks
#define NTH   256

#define SWZ(x) ((x) ^ (((x) >> 3) & 0x70))

// smem: A planes [buf][3][64*128B], B planes [buf][3][64*128B] -> 96KB
#define A_TILE 8192
#define B_TILE 8192
#define SOFF_A 0
#define SOFF_B (6 * A_TILE)                 // 49152
#define SMEM_TOTAL (SOFF_B + 6 * B_TILE)    // 98304

// W pre-split planes, already in swizzled tile layout: [kc][plane][tile 8KB]
__device__ __align__(16) uint32_t gWs[NCH * 3 * 2048];

// ---- exact 3-way bf16 split of two floats -> 3 packed bf16x2 words ----
__device__ __forceinline__ void split2(float x0, float x1,
                                       uint32_t& w0, uint32_t& w1, uint32_t& w2) {
    const uint32_t M = 0xFFFF0000u;
    uint32_t u0 = __float_as_uint(x0), u1 = __float_as_uint(x1);
    float r0 = x0 - __uint_as_float(u0 & M);
    float r1 = x1 - __uint_as_float(u1 & M);
    uint32_t v0 = __float_as_uint(r0), v1 = __float_as_uint(r1);
    float s0 = r0 - __uint_as_float(v0 & M);
    float s1 = r1 - __uint_as_float(v1 & M);
    w0 = __byte_perm(u0, u1, 0x7632);
    w1 = __byte_perm(v0, v1, 0x7632);
    w2 = __byte_perm(__float_as_uint(s0), __float_as_uint(s1), 0x7632);
}

__device__ __forceinline__ uint32_t s2u(const void* p) {
    uint32_t a;
    asm("{ .reg .u64 t; cvta.to.shared.u64 t, %1; cvt.u32.u64 %0, t; }" : "=r"(a) : "l"(p));
    return a;
}

__device__ __forceinline__ void ldm4(uint32_t* r, uint32_t addr) {
    asm volatile("ldmatrix.sync.aligned.m8n8.x4.shared.b16 {%0,%1,%2,%3}, [%4];"
                 : "=r"(r[0]), "=r"(r[1]), "=r"(r[2]), "=r"(r[3]) : "r"(addr));
}

__device__ __forceinline__ void mma16816(float* d, const uint32_t* a,
                                         uint32_t b0, uint32_t b1) {
    asm volatile("mma.sync.aligned.m16n8k16.row.col.f32.bf16.bf16.f32 "
                 "{%0,%1,%2,%3}, {%4,%5,%6,%7}, {%8,%9}, {%0,%1,%2,%3};"
                 : "+f"(d[0]), "+f"(d[1]), "+f"(d[2]), "+f"(d[3])
                 : "r"(a[0]), "r"(a[1]), "r"(a[2]), "r"(a[3]), "r"(b0), "r"(b1));
}

#define CP16(s, g) \
    asm volatile("cp.async.cg.shared.global [%0], [%1], 16;" :: "r"(s), "l"(g))
#define CP_COMMIT() asm volatile("cp.async.commit_group;" ::: "memory")
#define CP_WAIT0()  asm volatile("cp.async.wait_group 0;" ::: "memory")

// ---- kernel 0: split W once into swizzled bf16 plane tiles ----
__global__ __launch_bounds__(256)
void split_w_kernel(const float* __restrict__ W) {
    const int j = blockIdx.x * 256 + threadIdx.x;   // pair index, 0..131071
    const int e  = j >> 11;                          // expert 0..63
    const int k0 = (j & 2047) << 1;                  // even k
    float x0 = W[e * DDIM + k0];
    float x1 = W[e * DDIM + k0 + 1];
    uint32_t w0, w1, w2;
    split2(x0, x1, w0, w1, w2);
    const int kc  = k0 >> 6;
    const int off = SWZ(e * 128 + (k0 & 63) * 2) >> 2;   // u32 index in tile
    gWs[(kc * 3 + 0) * 2048 + off] = w0;
    gWs[(kc * 3 + 1) * 2048 + off] = w1;
    gWs[(kc * 3 + 2) * 2048 + off] = w2;
}

// ---- main kernel: 64 tokens x 64 experts per CTA, 2 CTAs/SM ----
__global__ __launch_bounds__(NTH, 2)
void gate_kernel(const float* __restrict__ h, float* __restrict__ out)
{
    extern __shared__ __align__(16) char smem[];
    const uint32_t sbase = s2u(smem);
    const int tid = threadIdx.x;
    const int wid = tid >> 5;
    const int lid = tid & 31;

    const float* hblk = h + (size_t)blockIdx.x * MROWS * DDIM;
    const uint4* gw = (const uint4*)gWs;   // 1536 uint4 per chunk (3 planes)

    float acc[4][4];
#pragma unroll
    for (int f = 0; f < 4; f++)
#pragma unroll
        for (int c = 0; c < 4; c++) acc[f][c] = 0.f;

    float4 areg[4];

    // loader mapping for A: 64 rows x 16 float4
    // warp tile: tokens mbase..+15, experts nbase..+31
    const int mbase = (wid & 3) << 4;
    const int nbase = (wid >> 2) << 5;
    const int arow  = mbase + (lid & 15);
    const int ax    = (lid >> 4) << 4;
    const int arx   = (arow & 7) << 4;
    const int brow  = ((lid >> 4) << 3) + (lid & 7);
    const int bx    = ((lid >> 3) & 1) << 4;
    const int brx   = (lid & 7) << 4;

    // ---- prologue: chunk 0 ----
#pragma unroll
    for (int i = 0; i < 4; i++) {
        const int q = tid + NTH * i;
        areg[i] = *(const float4*)(hblk + (size_t)(q >> 4) * DDIM + (q & 15) * 4);
    }
    {
        const uint32_t sB0 = sbase + SOFF_B;
#pragma unroll
        for (int i = 0; i < 6; i++) {
            const int idx = tid + NTH * i;
            CP16(sB0 + idx * 16, gw + idx);
        }
        CP_COMMIT();
        char* ab = smem + SOFF_A;
#pragma unroll
        for (int i = 0; i < 4; i++) {
            const int q = tid + NTH * i;
            uint32_t a0, a1, a2, b0, b1, b2;
            split2(areg[i].x, areg[i].y, a0, a1, a2);
            split2(areg[i].z, areg[i].w, b0, b1, b2);
            const int off = SWZ((q >> 4) * 128 + (q & 15) * 8);
            *(uint2*)(ab + off)              = make_uint2(a0, b0);
            *(uint2*)(ab + A_TILE + off)     = make_uint2(a1, b1);
            *(uint2*)(ab + 2 * A_TILE + off) = make_uint2(a2, b2);
        }
        CP_WAIT0();
    }
    __syncthreads();

    for (int kc = 0; kc < NCH; ++kc) {
        const int buf = kc & 1;
        const int nb  = buf ^ 1;

        // prefetch next chunk: A -> regs, B -> cp.async into other buffer
        if (kc + 1 < NCH) {
            const float* hp = hblk + (kc + 1) * KC;
#pragma unroll
            for (int i = 0; i < 4; i++) {
                const int q = tid + NTH * i;
                areg[i] = *(const float4*)(hp + (size_t)(q >> 4) * DDIM + (q & 15) * 4);
            }
            const uint4* gp = gw + (size_t)(kc + 1) * 1536;
            const uint32_t sBn = sbase + SOFF_B + nb * 3 * B_TILE;
#pragma unroll
            for (int i = 0; i < 6; i++) {
                const int idx = tid + NTH * i;
                CP16(sBn + idx * 16, gp + idx);
            }
            CP_COMMIT();
        }

        // ---- MMA on current buffer ----
        const uint32_t sA = sbase + SOFF_A + buf * 3 * A_TILE;
        const uint32_t sB = sbase + SOFF_B + buf * 3 * B_TILE;
#pragma unroll
        for (int ks = 0; ks < 4; ++ks) {
            uint32_t a[3][4];
#pragma unroll
            for (int s = 0; s < 3; s++)
                ldm4(a[s], sA + s * A_TILE + arow * 128 + ((ks * 32 + ax) ^ arx));
#pragma unroll
            for (int nbi = 0; nbi < 2; ++nbi) {
                uint32_t b[3][4];
#pragma unroll
                for (int s = 0; s < 3; s++)
                    ldm4(b[s], sB + s * B_TILE + (nbase + nbi * 16 + brow) * 128
                               + ((ks * 32 + bx) ^ brx));
                const int f = nbi * 2;
                // 6 split products: hh, hm, mh, mm, hl, lh
                mma16816(acc[f], a[0], b[0][0], b[0][1]);
                mma16816(acc[f + 1], a[0], b[0][2], b[0][3]);
                mma16816(acc[f], a[0], b[1][0], b[1][1]);
                mma16816(acc[f + 1], a[0], b[1][2], b[1][3]);
                mma16816(acc[f], a[1], b[0][0], b[0][1]);
                mma16816(acc[f + 1], a[1], b[0][2], b[0][3]);
                mma16816(acc[f], a[1], b[1][0], b[1][1]);
                mma16816(acc[f + 1], a[1], b[1][2], b[1][3]);
                mma16816(acc[f], a[0], b[2][0], b[2][1]);
                mma16816(acc[f + 1], a[0], b[2][2], b[2][3]);
                mma16816(acc[f], a[2], b[0][0], b[0][1]);
                mma16816(acc[f + 1], a[2], b[0][2], b[0][3]);
            }
        }

        // ---- store prefetched A into other buffer; drain B cp.async ----
        if (kc + 1 < NCH) {
            char* ab = smem + SOFF_A + nb * 3 * A_TILE;
#pragma unroll
            for (int i = 0; i < 4; i++) {
                const int q = tid + NTH * i;
                uint32_t a0, a1, a2, b0, b1, b2;
                split2(areg[i].x, areg[i].y, a0, a1, a2);
                split2(areg[i].z, areg[i].w, b0, b1, b2);
                const int off = SWZ((q >> 4) * 128 + (q & 15) * 8);
                *(uint2*)(ab + off)              = make_uint2(a0, b0);
                *(uint2*)(ab + A_TILE + off)     = make_uint2(a1, b1);
                *(uint2*)(ab + 2 * A_TILE + off) = make_uint2(a2, b2);
            }
            CP_WAIT0();
        }
        __syncthreads();
    }

    // ---- epilogue: logits -> smem [64][66] ----
    float* lg = (float*)smem;
#pragma unroll
    for (int nbi = 0; nbi < 2; ++nbi) {
#pragma unroll
        for (int p = 0; p < 2; ++p) {
            const int f = nbi * 2 + p;
            const int col = nbase + nbi * 16 + p * 8 + (lid & 3) * 2;
            const int r0  = mbase + (lid >> 2);
            *(float2*)(lg + r0 * 66 + col)       = make_float2(acc[f][0], acc[f][1]);
            *(float2*)(lg + (r0 + 8) * 66 + col) = make_float2(acc[f][2], acc[f][3]);
        }
    }
    __syncthreads();

    if (tid < MROWS) {
        const float* row = lg + tid * 66;
        float v1 = -1e30f, v2 = -1e30f;
        int i1 = 0, i2 = 0;
#pragma unroll 8
        for (int e = 0; e < NEXP; ++e) {
            float l = row[e];
            if (l > v1) { v2 = v1; i2 = i1; v1 = l; i1 = e; }
            else if (l > v2) { v2 = l; i2 = e; }
        }
        float S = 0.f;
#pragma unroll 8
        for (int e = 0; e < NEXP; ++e) S += __expf(row[e] - v1);
        const float e1  = __expf(v2 - v1);
        const float den = 1.0f + e1 + 1e-9f * S;

        const size_t gt = (size_t)blockIdx.x * MROWS + tid;
        out[gt * 2 + 0] = 1.0f / den;
        out[gt * 2 + 1] = e1 / den;
        out[(size_t)2 * TTOK + gt * 2 + 0] = (float)i1;
        out[(size_t)2 * TTOK + gt * 2 + 1] = (float)i2;
    }
}

extern "C" void kernel_launch(void* const* d_in, const int* in_sizes, int n_in,
                              void* d_out, int out_size)
{
    const float* h = (const float*)d_in[0];
    const float* W = (const float*)d_in[1];
    float* out = (float*)d_out;

    split_w_kernel<<<512, 256>>>(W);

    static int smem_set = 0;
    if (!smem_set) {
        cudaFuncSetAttribute(gate_kernel, cudaFuncAttributeMaxDynamicSharedMemorySize,
                             SMEM_TOTAL);
        smem_set = 1;
    }
    gate_kernel<<<TTOK / MROWS, NTH, SMEM_TOTAL>>>(h, out);
}

// round 7
// speedup vs baseline: 3.7721x; 1.5879x over previous
#include <cuda_runtime.h>
#include <cuda_fp16.h>
#include <cstdint>

#define TTOK  16384
#define DDIM  4096
#define NEXP  64
#define MROWS 64                // tokens per CTA
#define KC    64                // k per chunk (64 fp16 = 128B rows, SW128)
#define NCH   (DDIM / KC)       // 64 chunks
#define NTH   256

#define SWZ(x) ((x) ^ (((x) >> 3) & 0x70))

// smem: A planes [buf][2][64*128B] = 32KB, B planes [buf][2][64*128B] = 32KB
#define A_TILE 8192
#define B_TILE 8192
#define SOFF_A 0
#define SOFF_B (4 * A_TILE)                 // 32768
#define SMEM_TOTAL (SOFF_B + 4 * B_TILE)    // 65536

#define LO_SCALE   2048.0f
#define LO_INV     4.8828125e-4f            // 1/2048

// W pre-split planes, swizzled tile layout: [kc][plane(2)][2048 u32]
__device__ __align__(16) uint32_t gWs[NCH * 2 * 2048];

// ---- exact fp16 2-way split of two floats; lo pre-scaled by 2048 ----
__device__ __forceinline__ void split2h(float x0, float x1,
                                        uint32_t& whi, uint32_t& wlo) {
    __half2 hh = __float22half2_rn(make_float2(x0, x1));
    float2 back = __half22float2(hh);
    float r0 = (x0 - back.x) * LO_SCALE;
    float r1 = (x1 - back.y) * LO_SCALE;
    __half2 ll = __float22half2_rn(make_float2(r0, r1));
    whi = *(uint32_t*)&hh;
    wlo = *(uint32_t*)&ll;
}

__device__ __forceinline__ uint32_t s2u(const void* p) {
    uint32_t a;
    asm("{ .reg .u64 t; cvta.to.shared.u64 t, %1; cvt.u32.u64 %0, t; }" : "=r"(a) : "l"(p));
    return a;
}

__device__ __forceinline__ void ldm4(uint32_t* r, uint32_t addr) {
    asm volatile("ldmatrix.sync.aligned.m8n8.x4.shared.b16 {%0,%1,%2,%3}, [%4];"
                 : "=r"(r[0]), "=r"(r[1]), "=r"(r[2]), "=r"(r[3]) : "r"(addr));
}

__device__ __forceinline__ void mma16816(float* d, const uint32_t* a,
                                         uint32_t b0, uint32_t b1) {
    asm volatile("mma.sync.aligned.m16n8k16.row.col.f32.f16.f16.f32 "
                 "{%0,%1,%2,%3}, {%4,%5,%6,%7}, {%8,%9}, {%0,%1,%2,%3};"
                 : "+f"(d[0]), "+f"(d[1]), "+f"(d[2]), "+f"(d[3])
                 : "r"(a[0]), "r"(a[1]), "r"(a[2]), "r"(a[3]), "r"(b0), "r"(b1));
}

#define CP16(s, g) \
    asm volatile("cp.async.cg.shared.global [%0], [%1], 16;" :: "r"(s), "l"(g))
#define CP_COMMIT() asm volatile("cp.async.commit_group;" ::: "memory")
#define CP_WAIT0()  asm volatile("cp.async.wait_group 0;" ::: "memory")

// ---- kernel 0: split W once into swizzled fp16 plane tiles ----
__global__ __launch_bounds__(256)
void split_w_kernel(const float* __restrict__ W) {
    const int j = blockIdx.x * 256 + threadIdx.x;   // pair index, 0..131071
    const int e  = j >> 11;                          // expert 0..63
    const int k0 = (j & 2047) << 1;                  // even k
    float x0 = W[e * DDIM + k0];
    float x1 = W[e * DDIM + k0 + 1];
    uint32_t whi, wlo;
    split2h(x0, x1, whi, wlo);
    const int kc  = k0 >> 6;
    const int off = SWZ(e * 128 + (k0 & 63) * 2) >> 2;   // u32 index in tile
    gWs[(kc * 2 + 0) * 2048 + off] = whi;
    gWs[(kc * 2 + 1) * 2048 + off] = wlo;
}

// ---- main kernel: 64 tokens x 64 experts per CTA, 2 CTAs/SM ----
__global__ __launch_bounds__(NTH, 2)
void gate_kernel(const float* __restrict__ h, float* __restrict__ out)
{
    extern __shared__ __align__(16) char smem[];
    const uint32_t sbase = s2u(smem);
    const int tid = threadIdx.x;
    const int wid = tid >> 5;
    const int lid = tid & 31;

    const float* hblk = h + (size_t)blockIdx.x * MROWS * DDIM;
    const uint4* gw = (const uint4*)gWs;   // 1024 uint4 per chunk (2 planes)

    float accH[4][4], accL[4][4];
#pragma unroll
    for (int f = 0; f < 4; f++)
#pragma unroll
        for (int c = 0; c < 4; c++) { accH[f][c] = 0.f; accL[f][c] = 0.f; }

    float4 areg[4];

    // warp tile: tokens mbase..+15, experts nbase..+31
    const int mbase = (wid & 3) << 4;
    const int nbase = (wid >> 2) << 5;
    const int arow  = mbase + (lid & 15);
    const int ax    = (lid >> 4) << 4;
    const int arx   = (arow & 7) << 4;
    const int brow  = ((lid >> 4) << 3) + (lid & 7);
    const int bx    = ((lid >> 3) & 1) << 4;
    const int brx   = (lid & 7) << 4;

    // ---- prologue: chunk 0 ----
#pragma unroll
    for (int i = 0; i < 4; i++) {
        const int q = tid + NTH * i;
        areg[i] = *(const float4*)(hblk + (size_t)(q >> 4) * DDIM + (q & 15) * 4);
    }
    {
        const uint32_t sB0 = sbase + SOFF_B;
#pragma unroll
        for (int i = 0; i < 4; i++) {
            const int idx = tid + NTH * i;
            CP16(sB0 + idx * 16, gw + idx);
        }
        CP_COMMIT();
        char* ab = smem + SOFF_A;
#pragma unroll
        for (int i = 0; i < 4; i++) {
            const int q = tid + NTH * i;
            uint32_t h0, l0, h1, l1;
            split2h(areg[i].x, areg[i].y, h0, l0);
            split2h(areg[i].z, areg[i].w, h1, l1);
            const int off = SWZ((q >> 4) * 128 + (q & 15) * 8);
            *(uint2*)(ab + off)          = make_uint2(h0, h1);
            *(uint2*)(ab + A_TILE + off) = make_uint2(l0, l1);
        }
        CP_WAIT0();
    }
    __syncthreads();

    for (int kc = 0; kc < NCH; ++kc) {
        const int buf = kc & 1;
        const int nb  = buf ^ 1;

        // prefetch next chunk: A -> regs, B -> cp.async into other buffer
        if (kc + 1 < NCH) {
            const float* hp = hblk + (kc + 1) * KC;
#pragma unroll
            for (int i = 0; i < 4; i++) {
                const int q = tid + NTH * i;
                areg[i] = *(const float4*)(hp + (size_t)(q >> 4) * DDIM + (q & 15) * 4);
            }
            const uint4* gp = gw + (size_t)(kc + 1) * 1024;
            const uint32_t sBn = sbase + SOFF_B + nb * 2 * B_TILE;
#pragma unroll
            for (int i = 0; i < 4; i++) {
                const int idx = tid + NTH * i;
                CP16(sBn + idx * 16, gp + idx);
            }
            CP_COMMIT();
        }

        // ---- MMA on current buffer ----
        const uint32_t sA = sbase + SOFF_A + buf * 2 * A_TILE;
        const uint32_t sB = sbase + SOFF_B + buf * 2 * B_TILE;
#pragma unroll
        for (int ks = 0; ks < 4; ++ks) {
            uint32_t a[2][4];
            ldm4(a[0], sA + arow * 128 + ((ks * 32 + ax) ^ arx));
            ldm4(a[1], sA + A_TILE + arow * 128 + ((ks * 32 + ax) ^ arx));
            uint32_t b[2][2][4];   // [nbi][plane][frag]
#pragma unroll
            for (int nbi = 0; nbi < 2; ++nbi) {
                const uint32_t baddr = sB + (nbase + nbi * 16 + brow) * 128
                                       + ((ks * 32 + bx) ^ brx);
                ldm4(b[nbi][0], baddr);
                ldm4(b[nbi][1], baddr + B_TILE);
            }
            // 12 mma, interleaved across 4 independent acc chains
            mma16816(accH[0], a[0], b[0][0][0], b[0][0][1]);   // hh n0 lo-half
            mma16816(accH[2], a[0], b[1][0][0], b[1][0][1]);   // hh n1
            mma16816(accH[1], a[0], b[0][0][2], b[0][0][3]);
            mma16816(accH[3], a[0], b[1][0][2], b[1][0][3]);
            mma16816(accL[0], a[0], b[0][1][0], b[0][1][1]);   // hi_h * lo_W
            mma16816(accL[2], a[0], b[1][1][0], b[1][1][1]);
            mma16816(accL[1], a[0], b[0][1][2], b[0][1][3]);
            mma16816(accL[3], a[0], b[1][1][2], b[1][1][3]);
            mma16816(accL[0], a[1], b[0][0][0], b[0][0][1]);   // lo_h * hi_W
            mma16816(accL[2], a[1], b[1][0][0], b[1][0][1]);
            mma16816(accL[1], a[1], b[0][0][2], b[0][0][3]);
            mma16816(accL[3], a[1], b[1][0][2], b[1][0][3]);
        }

        // ---- store prefetched A into other buffer; drain B cp.async ----
        if (kc + 1 < NCH) {
            char* ab = smem + SOFF_A + nb * 2 * A_TILE;
#pragma unroll
            for (int i = 0; i < 4; i++) {
                const int q = tid + NTH * i;
                uint32_t h0, l0, h1, l1;
                split2h(areg[i].x, areg[i].y, h0, l0);
                split2h(areg[i].z, areg[i].w, h1, l1);
                const int off = SWZ((q >> 4) * 128 + (q & 15) * 8);
                *(uint2*)(ab + off)          = make_uint2(h0, h1);
                *(uint2*)(ab + A_TILE + off) = make_uint2(l0, l1);
            }
            CP_WAIT0();
        }
        __syncthreads();
    }

    // ---- combine planes: logit = accH + accL/2048 ----
    float acc[4][4];
#pragma unroll
    for (int f = 0; f < 4; f++)
#pragma unroll
        for (int c = 0; c < 4; c++)
            acc[f][c] = fmaf(accL[f][c], LO_INV, accH[f][c]);

    // ---- epilogue: logits -> smem [64][66] ----
    float* lg = (float*)smem;
#pragma unroll
    for (int nbi = 0; nbi < 2; ++nbi) {
#pragma unroll
        for (int p = 0; p < 2; ++p) {
            const int f = nbi * 2 + p;
            const int col = nbase + nbi * 16 + p * 8 + (lid & 3) * 2;
            const int r0  = mbase + (lid >> 2);
            *(float2*)(lg + r0 * 66 + col)       = make_float2(acc[f][0], acc[f][1]);
            *(float2*)(lg + (r0 + 8) * 66 + col) = make_float2(acc[f][2], acc[f][3]);
        }
    }
    __syncthreads();

    if (tid < MROWS) {
        const float* row = lg + tid * 66;
        float v1 = -1e30f, v2 = -1e30f;
        int i1 = 0, i2 = 0;
#pragma unroll 8
        for (int e = 0; e < NEXP; ++e) {
            float l = row[e];
            if (l > v1) { v2 = v1; i2 = i1; v1 = l; i1 = e; }
            else if (l > v2) { v2 = l; i2 = e; }
        }
        float S = 0.f;
#pragma unroll 8
        for (int e = 0; e < NEXP; ++e) S += __expf(row[e] - v1);
        const float e1  = __expf(v2 - v1);
        const float den = 1.0f + e1 + 1e-9f * S;

        const size_t gt = (size_t)blockIdx.x * MROWS + tid;
        out[gt * 2 + 0] = 1.0f / den;
        out[gt * 2 + 1] = e1 / den;
        out[(size_t)2 * TTOK + gt * 2 + 0] = (float)i1;
        out[(size_t)2 * TTOK + gt * 2 + 1] = (float)i2;
    }
}

extern "C" void kernel_launch(void* const* d_in, const int* in_sizes, int n_in,
                              void* d_out, int out_size)
{
    const float* h = (const float*)d_in[0];
    const float* W = (const float*)d_in[1];
    float* out = (float*)d_out;

    split_w_kernel<<<512, 256>>>(W);

    static int smem_set = 0;
    if (!smem_set) {
        cudaFuncSetAttribute(gate_kernel, cudaFuncAttributeMaxDynamicSharedMemorySize,
                             SMEM_TOTAL);
        smem_set = 1;
    }
    gate_kernel<<<TTOK / MROWS, NTH, SMEM_TOTAL>>>(h, out);
}